// round 15
// baseline (speedup 1.0000x reference)
#include <cuda_runtime.h>
#include <cuda_fp16.h>

// Problem shape (fixed by the dataset)
#define NN      50000
#define FIN     128
#define HF      128          // H * F_OUT
#define NHEAD   4
#define FOUT    32
#define EDGES   1600000
#define CAP     128          // slot capacity per dst (max degree ~60, Poisson(32))

// GEMM smem: A tile 128x136 halves + B tile 128x136 halves (col-major)
#define T_STRIDE 136
#define TILE_HALVES (128 * T_STRIDE)            // 17408
#define GEMM_SMEM_BYTES (2 * TILE_HALVES * 2)   // 69,632 B

// ---------------- scratch (static __device__, no allocation) ----------------
// g_key rows are PERMUTED (see perm_col): line A = halves [0,64) holds the
// first 8 features of each lane-chunk, line B = halves [64,128) the second 8.
// 256B-aligned so each row's two halves are exactly two 128B lines.
__device__ __align__(256) __half g_key[NN * HF];     // 12.8 MB, L2-resident
__device__ __align__(16) float  g_sdst[NN * NHEAD];  // 800 KB
__device__ __align__(16) float  g_ssrc[NN * NHEAD];  // 800 KB
__device__ __align__(16) __half g_Wh[TILE_HALVES];   // W, fp16, col-major padded
__device__ int g_counts[NN];                         // per-dst fill cursor
__device__ int g_slots[NN * CAP];                    // 25.6 MB: src lists per dst

// ---------------------------------------------------------------------------
// helpers
// ---------------------------------------------------------------------------
__device__ __forceinline__ void mma_f16(float c[4], const unsigned a[4], const unsigned b[2])
{
    asm volatile(
        "mma.sync.aligned.m16n8k16.row.col.f32.f16.f16.f32 "
        "{%0,%1,%2,%3}, {%4,%5,%6,%7}, {%8,%9}, {%0,%1,%2,%3};\n"
        : "+f"(c[0]), "+f"(c[1]), "+f"(c[2]), "+f"(c[3])
        : "r"(a[0]), "r"(a[1]), "r"(a[2]), "r"(a[3]), "r"(b[0]), "r"(b[1]));
}

__device__ __forceinline__ void cp16(void* s, const void* g)
{
    unsigned sa = (unsigned)__cvta_generic_to_shared(s);
    asm volatile("cp.async.cg.shared.global [%0], [%1], 16;\n" :: "r"(sa), "l"(g));
}
__device__ __forceinline__ void cp_commit()
{
    asm volatile("cp.async.commit_group;\n");
}
__device__ __forceinline__ void cp_wait_all()
{
    asm volatile("cp.async.wait_group 0;\n");
}

// packed f32x2 helpers (Blackwell dual-FMA pipe)
__device__ __forceinline__ unsigned long long pack2(float lo, float hi)
{
    unsigned long long p;
    asm("mov.b64 %0, {%1,%2};" : "=l"(p) : "f"(lo), "f"(hi));
    return p;
}
__device__ __forceinline__ void fma2(unsigned long long& acc, __half2 h2,
                                     unsigned long long wp)
{
    float2 f = __half22float2(h2);
    unsigned long long fp = pack2(f.x, f.y);
    asm("fma.rn.f32x2 %0, %1, %2, %0;" : "+l"(acc) : "l"(fp), "l"(wp));
}
__device__ __forceinline__ float2 unpack2(unsigned long long p)
{
    float2 f;
    asm("mov.b64 {%0,%1}, %2;" : "=f"(f.x), "=f"(f.y) : "l"(p));
    return f;
}

// key-row column permutation: natural feature c -> stored position.
// lane-chunk hl2 = (head<<1)|(bit4 of sub), j = sub&15.
// j<8 -> lineA at hl2*8+j ; j>=8 -> lineB at 64+hl2*8+(j-8).
__device__ __forceinline__ int perm_col(int c)
{
    int h   = c >> 5;
    int sub = c & 31;
    int hl2 = (h << 1) | (sub >> 4);
    int j   = sub & 15;
    return (j < 8) ? (hl2 * 8 + j) : (64 + hl2 * 8 + (j - 8));
}

// ---------------------------------------------------------------------------
// 0) prep: W (128x128 fp32, row-major k x col) -> g_Wh (col-major fp16)
// ---------------------------------------------------------------------------
__global__ void prep_w_kernel(const float* __restrict__ W)
{
    int t = blockIdx.x * blockDim.x + threadIdx.x;    // 0..16383
    int c = t >> 7, k = t & 127;
    g_Wh[c * T_STRIDE + k] = __float2half(W[k * HF + c]);
}

// ---------------------------------------------------------------------------
// 1) fp16 tensor-core GEMM, 128x128 tile, whole-K resident in smem.
//    Fused epilogue: +bias, PERMUTED fp16 key store, attention dots.
// ---------------------------------------------------------------------------
__global__ void __launch_bounds__(256, 2)
gemm_kernel(const float* __restrict__ A,
            const float* __restrict__ bias,
            const float* __restrict__ a_w,
            int n)
{
    extern __shared__ __half smh[];
    __half* As = smh;                  // [row][k], stride 136
    __half* Bh = smh + TILE_HALVES;    // [col][k], stride 136

    const int tid   = threadIdx.x;
    const int lane  = tid & 31;
    const int wid   = tid >> 5;
    const int wm    = (wid & 3) * 32;
    const int wn    = (wid >> 2) * 64;
    const int g     = lane >> 2;
    const int tg    = lane & 3;
    const int rowB  = blockIdx.x * 128;

    // ---- B: flat async copy of pre-converted W (34,816 B = 2176 x 16B) ----
    {
        const char* src = (const char*)g_Wh;
        char* dst = (char*)Bh;
#pragma unroll
        for (int j = 0; j < 9; j++) {
            int lin = j * 256 + tid;
            if (lin < 2176) cp16(dst + lin * 16, src + lin * 16);
        }
        cp_commit();
    }

    // ---- A: load fp32, convert to fp16, STS.64 (conflict-free) ----
#pragma unroll
    for (int j = 0; j < 16; j++) {
        int lin = j * 256 + tid;
        int r = lin >> 5, c4 = (lin & 31) << 2;
        int gr = rowB + r;
        float4 v = (gr < n) ? *(const float4*)&A[gr * FIN + c4]
                            : make_float4(0.f, 0.f, 0.f, 0.f);
        __half2 h0 = __floats2half2_rn(v.x, v.y);
        __half2 h1 = __floats2half2_rn(v.z, v.w);
        uint2 u;
        u.x = *(unsigned*)&h0;
        u.y = *(unsigned*)&h1;
        *(uint2*)&As[r * T_STRIDE + c4] = u;
    }

    cp_wait_all();
    __syncthreads();

    float acc[2][8][4];
#pragma unroll
    for (int mt = 0; mt < 2; mt++)
#pragma unroll
        for (int nt = 0; nt < 8; nt++)
#pragma unroll
            for (int r = 0; r < 4; r++) acc[mt][nt][r] = 0.f;

#pragma unroll
    for (int ks = 0; ks < 8; ks++) {
        int kk = ks * 16;
        unsigned a[2][4];
#pragma unroll
        for (int mt = 0; mt < 2; mt++) {
            int r0 = wm + mt * 16;
            a[mt][0] = *(const unsigned*)&As[(r0 + g)     * T_STRIDE + kk + 2 * tg];
            a[mt][1] = *(const unsigned*)&As[(r0 + g + 8) * T_STRIDE + kk + 2 * tg];
            a[mt][2] = *(const unsigned*)&As[(r0 + g)     * T_STRIDE + kk + 8 + 2 * tg];
            a[mt][3] = *(const unsigned*)&As[(r0 + g + 8) * T_STRIDE + kk + 8 + 2 * tg];
        }
        unsigned b[8][2];
#pragma unroll
        for (int nt = 0; nt < 8; nt++) {
            int col = wn + nt * 8 + g;
            b[nt][0] = *(const unsigned*)&Bh[col * T_STRIDE + kk + 2 * tg];
            b[nt][1] = *(const unsigned*)&Bh[col * T_STRIDE + kk + 8 + 2 * tg];
        }
#pragma unroll
        for (int mt = 0; mt < 2; mt++)
#pragma unroll
            for (int nt = 0; nt < 8; nt++)
                mma_f16(acc[mt][nt], a[mt], b[nt]);
    }

    // ---- epilogue: bias, permuted fp16 store, fused attention dots ----
    float sd[2][2][2], ss[2][2][2];
#pragma unroll
    for (int mt = 0; mt < 2; mt++)
#pragma unroll
        for (int hf = 0; hf < 2; hf++)
#pragma unroll
            for (int hl = 0; hl < 2; hl++) { sd[mt][hf][hl] = 0.f; ss[mt][hf][hl] = 0.f; }

#pragma unroll
    for (int nt = 0; nt < 8; nt++) {
        int cbase = wn + nt * 8 + tg * 2;
        int pcol  = perm_col(cbase);       // half2-safe (cbase even, j even)
        int hl    = nt >> 2;
        int head  = (wn >> 5) + hl;
        int cin   = cbase & 31;
        float b0 = __ldg(&bias[cbase]);
        float b1 = __ldg(&bias[cbase + 1]);
        float ad0 = __ldg(&a_w[head * 64 + cin]);
        float ad1 = __ldg(&a_w[head * 64 + cin + 1]);
        float as0 = __ldg(&a_w[head * 64 + 32 + cin]);
        float as1 = __ldg(&a_w[head * 64 + 32 + cin + 1]);
#pragma unroll
        for (int mt = 0; mt < 2; mt++) {
            int row0 = rowB + wm + mt * 16 + g;
            float v00 = acc[mt][nt][0] + b0;
            float v01 = acc[mt][nt][1] + b1;
            float v10 = acc[mt][nt][2] + b0;
            float v11 = acc[mt][nt][3] + b1;
            if (row0 < n)
                *(__half2*)&g_key[row0 * HF + pcol] = __floats2half2_rn(v00, v01);
            if (row0 + 8 < n)
                *(__half2*)&g_key[(row0 + 8) * HF + pcol] = __floats2half2_rn(v10, v11);
            sd[mt][0][hl] += v00 * ad0 + v01 * ad1;
            sd[mt][1][hl] += v10 * ad0 + v11 * ad1;
            ss[mt][0][hl] += v00 * as0 + v01 * as1;
            ss[mt][1][hl] += v10 * as0 + v11 * as1;
        }
    }
#pragma unroll
    for (int o = 1; o <= 2; o <<= 1) {
#pragma unroll
        for (int mt = 0; mt < 2; mt++)
#pragma unroll
            for (int hf = 0; hf < 2; hf++)
#pragma unroll
                for (int hl = 0; hl < 2; hl++) {
                    sd[mt][hf][hl] += __shfl_xor_sync(0xFFFFFFFFu, sd[mt][hf][hl], o);
                    ss[mt][hf][hl] += __shfl_xor_sync(0xFFFFFFFFu, ss[mt][hf][hl], o);
                }
    }
    if (tg == 0) {
#pragma unroll
        for (int mt = 0; mt < 2; mt++)
#pragma unroll
            for (int hf = 0; hf < 2; hf++) {
                int row = rowB + wm + mt * 16 + g + hf * 8;
                if (row < n) {
#pragma unroll
                    for (int hl = 0; hl < 2; hl++) {
                        int head = (wn >> 5) + hl;
                        g_sdst[row * NHEAD + head] = sd[mt][hf][hl];
                        g_ssrc[row * NHEAD + head] = ss[mt][hf][hl];
                    }
                }
            }
    }
}

// ---------------------------------------------------------------------------
// 2) single-pass bucket scatter (4B slot records)
// ---------------------------------------------------------------------------
__global__ void scatter_kernel(const int4* __restrict__ esrc4,
                               const int4* __restrict__ edst4, int e4)
{
    int i = blockIdx.x * blockDim.x + threadIdx.x;
    if (i >= e4) return;
    int4 s = esrc4[i];
    int4 d = edst4[i];
    int p;
    p = atomicAdd(&g_counts[d.x], 1); if (p < CAP) g_slots[d.x * CAP + p] = s.x;
    p = atomicAdd(&g_counts[d.y], 1); if (p < CAP) g_slots[d.y * CAP + p] = s.y;
    p = atomicAdd(&g_counts[d.z], 1); if (p < CAP) g_slots[d.z * CAP + p] = s.z;
    p = atomicAdd(&g_counts[d.w], 1); if (p < CAP) g_slots[d.w * CAP + p] = s.w;
}

// ---------------------------------------------------------------------------
// 3) aggregation: FOUR nodes per warp (8 lanes each, lane = 16 features),
//    permuted key rows: kA = row line A (one 128B line per node-group),
//    kB = row line B. Packed fma.rn.f32x2 fp32 accumulation.
// ---------------------------------------------------------------------------
__global__ void __launch_bounds__(128)
agg_kernel(const float* __restrict__ a_b, float* __restrict__ out, int n)
{
    int wid  = threadIdx.x >> 5;
    int lane = threadIdx.x & 31;
    int q    = lane >> 3;          // node slot within warp (0..3)
    int hl   = lane & 7;           // feature-lane within node (0..7)
    int node = blockIdx.x * 16 + wid * 4 + q;
    bool valid = node < n;
    int nodec = valid ? node : 0;
    int h = hl >> 1;               // head of this lane's 16-feature chunk

    const __half* keyA = g_key + hl * 8;        // line A lane slot
    const __half* keyB = g_key + 64 + hl * 8;   // line B lane slot
    float base_s = g_sdst[nodec * NHEAD + h] + __ldg(&a_b[h]);

    unsigned long long pA0, pA1, pA2, pA3, pB0, pB1, pB2, pB3;
    float dsum;
    {   // self edge
        float v = base_s + g_ssrc[nodec * NHEAD + h];
        v = fmaxf(v, 0.2f * v);
        float w = __expf(v);
        uint4 kA = *(const uint4*)&keyA[nodec * HF];
        uint4 kB = *(const uint4*)&keyB[nodec * HF];
        float2 f;
        f = __half22float2(*(__half2*)&kA.x); pA0 = pack2(w * f.x, w * f.y);
        f = __half22float2(*(__half2*)&kA.y); pA1 = pack2(w * f.x, w * f.y);
        f = __half22float2(*(__half2*)&kA.z); pA2 = pack2(w * f.x, w * f.y);
        f = __half22float2(*(__half2*)&kA.w); pA3 = pack2(w * f.x, w * f.y);
        f = __half22float2(*(__half2*)&kB.x); pB0 = pack2(w * f.x, w * f.y);
        f = __half22float2(*(__half2*)&kB.y); pB1 = pack2(w * f.x, w * f.y);
        f = __half22float2(*(__half2*)&kB.z); pB2 = pack2(w * f.x, w * f.y);
        f = __half22float2(*(__half2*)&kB.w); pB3 = pack2(w * f.x, w * f.y);
        dsum = w;
    }

    int cnt = valid ? min(g_counts[nodec], CAP) : 0;
    int cmax = cnt;
    cmax = max(cmax, __shfl_xor_sync(0xFFFFFFFFu, cmax, 8));
    cmax = max(cmax, __shfl_xor_sync(0xFFFFFFFFu, cmax, 16));
    const int* slots = g_slots + nodec * CAP;

    for (int i = 0; i < cmax; i += 2) {
        int2 s2 = *(const int2*)&slots[i];         // 8B-aligned broadcast
        int s0 = s2.x, s1 = s2.y;
        float v0 = base_s + __ldg(&g_ssrc[s0 * NHEAD + h]);
        float v1 = base_s + __ldg(&g_ssrc[s1 * NHEAD + h]);
        uint4 k0A = *(const uint4*)&keyA[s0 * HF];   // 1 line per node-group
        uint4 k0B = *(const uint4*)&keyB[s0 * HF];
        uint4 k1A = *(const uint4*)&keyA[s1 * HF];
        uint4 k1B = *(const uint4*)&keyB[s1 * HF];
        v0 = fmaxf(v0, 0.2f * v0);
        v1 = fmaxf(v1, 0.2f * v1);
        float w0 = (i     < cnt) ? __expf(v0) : 0.f;
        float w1 = (i + 1 < cnt) ? __expf(v1) : 0.f;
        unsigned long long wp0 = pack2(w0, w0);
        unsigned long long wp1 = pack2(w1, w1);
        fma2(pA0, *(__half2*)&k0A.x, wp0);
        fma2(pA1, *(__half2*)&k0A.y, wp0);
        fma2(pA2, *(__half2*)&k0A.z, wp0);
        fma2(pA3, *(__half2*)&k0A.w, wp0);
        fma2(pB0, *(__half2*)&k0B.x, wp0);
        fma2(pB1, *(__half2*)&k0B.y, wp0);
        fma2(pB2, *(__half2*)&k0B.z, wp0);
        fma2(pB3, *(__half2*)&k0B.w, wp0);
        fma2(pA0, *(__half2*)&k1A.x, wp1);
        fma2(pA1, *(__half2*)&k1A.y, wp1);
        fma2(pA2, *(__half2*)&k1A.z, wp1);
        fma2(pA3, *(__half2*)&k1A.w, wp1);
        fma2(pB0, *(__half2*)&k1B.x, wp1);
        fma2(pB1, *(__half2*)&k1B.y, wp1);
        fma2(pB2, *(__half2*)&k1B.z, wp1);
        fma2(pB3, *(__half2*)&k1B.w, wp1);
        dsum += w0 + w1;
    }

    if (valid) {
        float inv = __frcp_rn(dsum);
        float2 fA0 = unpack2(pA0), fA1 = unpack2(pA1);
        float2 fA2 = unpack2(pA2), fA3 = unpack2(pA3);
        float2 fB0 = unpack2(pB0), fB1 = unpack2(pB1);
        float2 fB2 = unpack2(pB2), fB3 = unpack2(pB3);
        // lane chunk = natural features hl*16 .. +15 (A = first 8, B = second 8)
        float4 o0 = make_float4(fA0.x * inv, fA0.y * inv, fA1.x * inv, fA1.y * inv);
        float4 o1 = make_float4(fA2.x * inv, fA2.y * inv, fA3.x * inv, fA3.y * inv);
        float4 o2 = make_float4(fB0.x * inv, fB0.y * inv, fB1.x * inv, fB1.y * inv);
        float4 o3 = make_float4(fB2.x * inv, fB2.y * inv, fB3.x * inv, fB3.y * inv);
        float* ob = &out[node * HF + hl * 16];
        *(float4*)&ob[0]  = o0;
        *(float4*)&ob[4]  = o1;
        *(float4*)&ob[8]  = o2;
        *(float4*)&ob[12] = o3;
    }
}

// ---------------------------------------------------------------------------
extern "C" void kernel_launch(void* const* d_in, const int* in_sizes, int n_in,
                              void* d_out, int out_size)
{
    const float* features = (const float*)d_in[0];
    const int*   esrc     = (const int*)d_in[1];
    const int*   edst     = (const int*)d_in[2];
    const float* Ww       = (const float*)d_in[3];
    const float* Wb       = (const float*)d_in[4];
    const float* aw       = (const float*)d_in[5];
    const float* ab       = (const float*)d_in[6];
    float*       out      = (float*)d_out;

    int n = in_sizes[0] / FIN;   // 50000
    int e = in_sizes[1];         // 1600000 (divisible by 4)
    int e4 = e >> 2;

    cudaFuncSetAttribute(gemm_kernel,
                         cudaFuncAttributeMaxDynamicSharedMemorySize,
                         GEMM_SMEM_BYTES);

    // lazy one-time side stream + fork/join events (created on the
    // uncaptured correctness call; captured as graph deps afterward)
    static cudaStream_t s2 = nullptr;
    static cudaEvent_t  evFork = nullptr, evJoin = nullptr;
    if (!s2) {
        cudaStreamCreateWithFlags(&s2, cudaStreamNonBlocking);
        cudaEventCreateWithFlags(&evFork, cudaEventDisableTiming);
        cudaEventCreateWithFlags(&evJoin, cudaEventDisableTiming);
    }

    void* counts_ptr = nullptr;
    cudaGetSymbolAddress(&counts_ptr, g_counts);

    // fork: prep+gemm (tensor/DRAM) on s2, memset+scatter (atomic/L2) on main
    cudaEventRecord(evFork, 0);
    cudaStreamWaitEvent(s2, evFork, 0);
    prep_w_kernel<<<64, 256, 0, s2>>>(Ww);
    gemm_kernel<<<(n + 127) / 128, 256, GEMM_SMEM_BYTES, s2>>>(features, Wb, aw, n);
    cudaEventRecord(evJoin, s2);

    cudaMemsetAsync(counts_ptr, 0, n * sizeof(int));
    scatter_kernel<<<(e4 + 255) / 256, 256>>>((const int4*)esrc, (const int4*)edst, e4);

    // join: agg needs gemm outputs (keys/scores) and scatter slot lists
    cudaStreamWaitEvent(0, evJoin, 0);
    agg_kernel<<<(n + 15) / 16, 128>>>(ab, out, n);
}

// round 16
// speedup vs baseline: 1.0543x; 1.0543x over previous
#include <cuda_runtime.h>
#include <cuda_fp16.h>

// Problem shape (fixed by the dataset)
#define NN      50000
#define FIN     128
#define HF      128          // H * F_OUT
#define NHEAD   4
#define FOUT    32
#define EDGES   1600000
#define CAP     128          // slot capacity per dst (max degree ~60, Poisson(32))

// GEMM smem: A tile 128x136 halves + B tile 128x136 halves (col-major)
#define T_STRIDE 136
#define TILE_HALVES (128 * T_STRIDE)            // 17408
#define GEMM_SMEM_BYTES (2 * TILE_HALVES * 2)   // 69,632 B

// ---------------- scratch (static __device__, no allocation) ----------------
// g_key rows are PERMUTED (see perm_col): line A = halves [0,64) holds the
// first 8 features of each lane-chunk, line B = halves [64,128) the second 8.
__device__ __align__(256) __half g_key[NN * HF];     // 12.8 MB, L2-resident
__device__ __align__(16) float  g_sdst[NN * NHEAD];  // 800 KB
__device__ __align__(16) float  g_ssrc[NN * NHEAD];  // 800 KB
__device__ __align__(16) __half g_Wh[TILE_HALVES];   // W, fp16, col-major padded
__device__ int g_counts[NN];                         // cursor; re-zeroed by agg
__device__ int g_slots[NN * CAP];                    // 25.6 MB: src lists per dst

// ---------------------------------------------------------------------------
// helpers
// ---------------------------------------------------------------------------
__device__ __forceinline__ void mma_f16(float c[4], const unsigned a[4], const unsigned b[2])
{
    asm volatile(
        "mma.sync.aligned.m16n8k16.row.col.f32.f16.f16.f32 "
        "{%0,%1,%2,%3}, {%4,%5,%6,%7}, {%8,%9}, {%0,%1,%2,%3};\n"
        : "+f"(c[0]), "+f"(c[1]), "+f"(c[2]), "+f"(c[3])
        : "r"(a[0]), "r"(a[1]), "r"(a[2]), "r"(a[3]), "r"(b[0]), "r"(b[1]));
}

__device__ __forceinline__ void cp16(void* s, const void* g)
{
    unsigned sa = (unsigned)__cvta_generic_to_shared(s);
    asm volatile("cp.async.cg.shared.global [%0], [%1], 16;\n" :: "r"(sa), "l"(g));
}
__device__ __forceinline__ void cp_commit()
{
    asm volatile("cp.async.commit_group;\n");
}
__device__ __forceinline__ void cp_wait_all()
{
    asm volatile("cp.async.wait_group 0;\n");
}

// packed f32x2 helpers (Blackwell dual-FMA pipe)
__device__ __forceinline__ unsigned long long pack2(float lo, float hi)
{
    unsigned long long p;
    asm("mov.b64 %0, {%1,%2};" : "=l"(p) : "f"(lo), "f"(hi));
    return p;
}
__device__ __forceinline__ void fma2(unsigned long long& acc, __half2 h2,
                                     unsigned long long wp)
{
    float2 f = __half22float2(h2);
    unsigned long long fp = pack2(f.x, f.y);
    asm("fma.rn.f32x2 %0, %1, %2, %0;" : "+l"(acc) : "l"(fp), "l"(wp));
}
__device__ __forceinline__ float2 unpack2(unsigned long long p)
{
    float2 f;
    asm("mov.b64 {%0,%1}, %2;" : "=f"(f.x), "=f"(f.y) : "l"(p));
    return f;
}

// key-row column permutation: natural feature c -> stored position.
__device__ __forceinline__ int perm_col(int c)
{
    int h   = c >> 5;
    int sub = c & 31;
    int hl2 = (h << 1) | (sub >> 4);
    int j   = sub & 15;
    return (j < 8) ? (hl2 * 8 + j) : (64 + hl2 * 8 + (j - 8));
}

// ---------------------------------------------------------------------------
// 0) prep: W (128x128 fp32, row-major k x col) -> g_Wh (col-major fp16)
// ---------------------------------------------------------------------------
__global__ void prep_w_kernel(const float* __restrict__ W)
{
    int t = blockIdx.x * blockDim.x + threadIdx.x;    // 0..16383
    int c = t >> 7, k = t & 127;
    g_Wh[c * T_STRIDE + k] = __float2half(W[k * HF + c]);
}

// ---------------------------------------------------------------------------
// 1) fp16 tensor-core GEMM, 128x128 tile, whole-K resident in smem.
//    Fused epilogue: +bias, PERMUTED fp16 key store, attention dots.
// ---------------------------------------------------------------------------
__global__ void __launch_bounds__(256, 2)
gemm_kernel(const float* __restrict__ A,
            const float* __restrict__ bias,
            const float* __restrict__ a_w,
            int n)
{
    extern __shared__ __half smh[];
    __half* As = smh;                  // [row][k], stride 136
    __half* Bh = smh + TILE_HALVES;    // [col][k], stride 136

    const int tid   = threadIdx.x;
    const int lane  = tid & 31;
    const int wid   = tid >> 5;
    const int wm    = (wid & 3) * 32;
    const int wn    = (wid >> 2) * 64;
    const int g     = lane >> 2;
    const int tg    = lane & 3;
    const int rowB  = blockIdx.x * 128;

    // ---- B: flat async copy of pre-converted W (34,816 B = 2176 x 16B) ----
    {
        const char* src = (const char*)g_Wh;
        char* dst = (char*)Bh;
#pragma unroll
        for (int j = 0; j < 9; j++) {
            int lin = j * 256 + tid;
            if (lin < 2176) cp16(dst + lin * 16, src + lin * 16);
        }
        cp_commit();
    }

    // ---- A: load fp32, convert to fp16, STS.64 (conflict-free) ----
#pragma unroll
    for (int j = 0; j < 16; j++) {
        int lin = j * 256 + tid;
        int r = lin >> 5, c4 = (lin & 31) << 2;
        int gr = rowB + r;
        float4 v = (gr < n) ? *(const float4*)&A[gr * FIN + c4]
                            : make_float4(0.f, 0.f, 0.f, 0.f);
        __half2 h0 = __floats2half2_rn(v.x, v.y);
        __half2 h1 = __floats2half2_rn(v.z, v.w);
        uint2 u;
        u.x = *(unsigned*)&h0;
        u.y = *(unsigned*)&h1;
        *(uint2*)&As[r * T_STRIDE + c4] = u;
    }

    cp_wait_all();
    __syncthreads();

    float acc[2][8][4];
#pragma unroll
    for (int mt = 0; mt < 2; mt++)
#pragma unroll
        for (int nt = 0; nt < 8; nt++)
#pragma unroll
            for (int r = 0; r < 4; r++) acc[mt][nt][r] = 0.f;

#pragma unroll
    for (int ks = 0; ks < 8; ks++) {
        int kk = ks * 16;
        unsigned a[2][4];
#pragma unroll
        for (int mt = 0; mt < 2; mt++) {
            int r0 = wm + mt * 16;
            a[mt][0] = *(const unsigned*)&As[(r0 + g)     * T_STRIDE + kk + 2 * tg];
            a[mt][1] = *(const unsigned*)&As[(r0 + g + 8) * T_STRIDE + kk + 2 * tg];
            a[mt][2] = *(const unsigned*)&As[(r0 + g)     * T_STRIDE + kk + 8 + 2 * tg];
            a[mt][3] = *(const unsigned*)&As[(r0 + g + 8) * T_STRIDE + kk + 8 + 2 * tg];
        }
        unsigned b[8][2];
#pragma unroll
        for (int nt = 0; nt < 8; nt++) {
            int col = wn + nt * 8 + g;
            b[nt][0] = *(const unsigned*)&Bh[col * T_STRIDE + kk + 2 * tg];
            b[nt][1] = *(const unsigned*)&Bh[col * T_STRIDE + kk + 8 + 2 * tg];
        }
#pragma unroll
        for (int mt = 0; mt < 2; mt++)
#pragma unroll
            for (int nt = 0; nt < 8; nt++)
                mma_f16(acc[mt][nt], a[mt], b[nt]);
    }

    // ---- epilogue: bias, permuted fp16 store, fused attention dots ----
    float sd[2][2][2], ss[2][2][2];
#pragma unroll
    for (int mt = 0; mt < 2; mt++)
#pragma unroll
        for (int hf = 0; hf < 2; hf++)
#pragma unroll
            for (int hl = 0; hl < 2; hl++) { sd[mt][hf][hl] = 0.f; ss[mt][hf][hl] = 0.f; }

#pragma unroll
    for (int nt = 0; nt < 8; nt++) {
        int cbase = wn + nt * 8 + tg * 2;
        int pcol  = perm_col(cbase);       // half2-safe (cbase even)
        int hl    = nt >> 2;
        int head  = (wn >> 5) + hl;
        int cin   = cbase & 31;
        float b0 = __ldg(&bias[cbase]);
        float b1 = __ldg(&bias[cbase + 1]);
        float ad0 = __ldg(&a_w[head * 64 + cin]);
        float ad1 = __ldg(&a_w[head * 64 + cin + 1]);
        float as0 = __ldg(&a_w[head * 64 + 32 + cin]);
        float as1 = __ldg(&a_w[head * 64 + 32 + cin + 1]);
#pragma unroll
        for (int mt = 0; mt < 2; mt++) {
            int row0 = rowB + wm + mt * 16 + g;
            float v00 = acc[mt][nt][0] + b0;
            float v01 = acc[mt][nt][1] + b1;
            float v10 = acc[mt][nt][2] + b0;
            float v11 = acc[mt][nt][3] + b1;
            if (row0 < n)
                *(__half2*)&g_key[row0 * HF + pcol] = __floats2half2_rn(v00, v01);
            if (row0 + 8 < n)
                *(__half2*)&g_key[(row0 + 8) * HF + pcol] = __floats2half2_rn(v10, v11);
            sd[mt][0][hl] += v00 * ad0 + v01 * ad1;
            sd[mt][1][hl] += v10 * ad0 + v11 * ad1;
            ss[mt][0][hl] += v00 * as0 + v01 * as1;
            ss[mt][1][hl] += v10 * as0 + v11 * as1;
        }
    }
#pragma unroll
    for (int o = 1; o <= 2; o <<= 1) {
#pragma unroll
        for (int mt = 0; mt < 2; mt++)
#pragma unroll
            for (int hf = 0; hf < 2; hf++)
#pragma unroll
                for (int hl = 0; hl < 2; hl++) {
                    sd[mt][hf][hl] += __shfl_xor_sync(0xFFFFFFFFu, sd[mt][hf][hl], o);
                    ss[mt][hf][hl] += __shfl_xor_sync(0xFFFFFFFFu, ss[mt][hf][hl], o);
                }
    }
    if (tg == 0) {
#pragma unroll
        for (int mt = 0; mt < 2; mt++)
#pragma unroll
            for (int hf = 0; hf < 2; hf++) {
                int row = rowB + wm + mt * 16 + g + hf * 8;
                if (row < n) {
#pragma unroll
                    for (int hl = 0; hl < 2; hl++) {
                        int head = (wn >> 5) + hl;
                        g_sdst[row * NHEAD + head] = sd[mt][hf][hl];
                        g_ssrc[row * NHEAD + head] = ss[mt][hf][hl];
                    }
                }
            }
    }
}

// ---------------------------------------------------------------------------
// 2) single-pass bucket scatter (4B slot records).
//    g_counts starts zeroed (.bss on call 1; re-zeroed by agg each call).
// ---------------------------------------------------------------------------
__global__ void scatter_kernel(const int4* __restrict__ esrc4,
                               const int4* __restrict__ edst4, int e4)
{
    int i = blockIdx.x * blockDim.x + threadIdx.x;
    if (i >= e4) return;
    int4 s = esrc4[i];
    int4 d = edst4[i];
    int p;
    p = atomicAdd(&g_counts[d.x], 1); if (p < CAP) g_slots[d.x * CAP + p] = s.x;
    p = atomicAdd(&g_counts[d.y], 1); if (p < CAP) g_slots[d.y * CAP + p] = s.y;
    p = atomicAdd(&g_counts[d.z], 1); if (p < CAP) g_slots[d.z * CAP + p] = s.z;
    p = atomicAdd(&g_counts[d.w], 1); if (p < CAP) g_slots[d.w * CAP + p] = s.w;
}

// ---------------------------------------------------------------------------
// 3) aggregation: FOUR nodes per warp (8 lanes each, lane = 16 features),
//    permuted key rows (1 line per node-group per load). 256-thread blocks.
//    Zeroes g_counts after reading (replaces the memset graph node).
// ---------------------------------------------------------------------------
__global__ void __launch_bounds__(256)
agg_kernel(const float* __restrict__ a_b, float* __restrict__ out, int n)
{
    int wid  = threadIdx.x >> 5;
    int lane = threadIdx.x & 31;
    int q    = lane >> 3;          // node slot within warp (0..3)
    int hl   = lane & 7;           // feature-lane within node (0..7)
    int node = blockIdx.x * 32 + wid * 4 + q;
    bool valid = node < n;
    int nodec = valid ? node : 0;
    int h = hl >> 1;               // head of this lane's 16-feature chunk

    const __half* keyA = g_key + hl * 8;        // line A lane slot
    const __half* keyB = g_key + 64 + hl * 8;   // line B lane slot
    float base_s = g_sdst[nodec * NHEAD + h] + __ldg(&a_b[h]);

    unsigned long long pA0, pA1, pA2, pA3, pB0, pB1, pB2, pB3;
    float dsum;
    {   // self edge
        float v = base_s + g_ssrc[nodec * NHEAD + h];
        v = fmaxf(v, 0.2f * v);
        float w = __expf(v);
        uint4 kA = *(const uint4*)&keyA[nodec * HF];
        uint4 kB = *(const uint4*)&keyB[nodec * HF];
        float2 f;
        f = __half22float2(*(__half2*)&kA.x); pA0 = pack2(w * f.x, w * f.y);
        f = __half22float2(*(__half2*)&kA.y); pA1 = pack2(w * f.x, w * f.y);
        f = __half22float2(*(__half2*)&kA.z); pA2 = pack2(w * f.x, w * f.y);
        f = __half22float2(*(__half2*)&kA.w); pA3 = pack2(w * f.x, w * f.y);
        f = __half22float2(*(__half2*)&kB.x); pB0 = pack2(w * f.x, w * f.y);
        f = __half22float2(*(__half2*)&kB.y); pB1 = pack2(w * f.x, w * f.y);
        f = __half22float2(*(__half2*)&kB.z); pB2 = pack2(w * f.x, w * f.y);
        f = __half22float2(*(__half2*)&kB.w); pB3 = pack2(w * f.x, w * f.y);
        dsum = w;
    }

    int cnt = valid ? min(g_counts[nodec], CAP) : 0;
    // re-zero the cursor for the next graph replay (one lane per node)
    if (valid && hl == 0) g_counts[nodec] = 0;
    int cmax = cnt;
    cmax = max(cmax, __shfl_xor_sync(0xFFFFFFFFu, cmax, 8));
    cmax = max(cmax, __shfl_xor_sync(0xFFFFFFFFu, cmax, 16));
    const int* slots = g_slots + nodec * CAP;

    for (int i = 0; i < cmax; i += 2) {
        int2 s2 = *(const int2*)&slots[i];         // 8B-aligned broadcast
        int s0 = s2.x, s1 = s2.y;
        float v0 = base_s + __ldg(&g_ssrc[s0 * NHEAD + h]);
        float v1 = base_s + __ldg(&g_ssrc[s1 * NHEAD + h]);
        uint4 k0A = *(const uint4*)&keyA[s0 * HF];   // 1 line per node-group
        uint4 k0B = *(const uint4*)&keyB[s0 * HF];
        uint4 k1A = *(const uint4*)&keyA[s1 * HF];
        uint4 k1B = *(const uint4*)&keyB[s1 * HF];
        v0 = fmaxf(v0, 0.2f * v0);
        v1 = fmaxf(v1, 0.2f * v1);
        float w0 = (i     < cnt) ? __expf(v0) : 0.f;
        float w1 = (i + 1 < cnt) ? __expf(v1) : 0.f;
        unsigned long long wp0 = pack2(w0, w0);
        unsigned long long wp1 = pack2(w1, w1);
        fma2(pA0, *(__half2*)&k0A.x, wp0);
        fma2(pA1, *(__half2*)&k0A.y, wp0);
        fma2(pA2, *(__half2*)&k0A.z, wp0);
        fma2(pA3, *(__half2*)&k0A.w, wp0);
        fma2(pB0, *(__half2*)&k0B.x, wp0);
        fma2(pB1, *(__half2*)&k0B.y, wp0);
        fma2(pB2, *(__half2*)&k0B.z, wp0);
        fma2(pB3, *(__half2*)&k0B.w, wp0);
        fma2(pA0, *(__half2*)&k1A.x, wp1);
        fma2(pA1, *(__half2*)&k1A.y, wp1);
        fma2(pA2, *(__half2*)&k1A.z, wp1);
        fma2(pA3, *(__half2*)&k1A.w, wp1);
        fma2(pB0, *(__half2*)&k1B.x, wp1);
        fma2(pB1, *(__half2*)&k1B.y, wp1);
        fma2(pB2, *(__half2*)&k1B.z, wp1);
        fma2(pB3, *(__half2*)&k1B.w, wp1);
        dsum += w0 + w1;
    }

    if (valid) {
        float inv = __frcp_rn(dsum);
        float2 fA0 = unpack2(pA0), fA1 = unpack2(pA1);
        float2 fA2 = unpack2(pA2), fA3 = unpack2(pA3);
        float2 fB0 = unpack2(pB0), fB1 = unpack2(pB1);
        float2 fB2 = unpack2(pB2), fB3 = unpack2(pB3);
        float4 o0 = make_float4(fA0.x * inv, fA0.y * inv, fA1.x * inv, fA1.y * inv);
        float4 o1 = make_float4(fA2.x * inv, fA2.y * inv, fA3.x * inv, fA3.y * inv);
        float4 o2 = make_float4(fB0.x * inv, fB0.y * inv, fB1.x * inv, fB1.y * inv);
        float4 o3 = make_float4(fB2.x * inv, fB2.y * inv, fB3.x * inv, fB3.y * inv);
        float* ob = &out[node * HF + hl * 16];
        *(float4*)&ob[0]  = o0;
        *(float4*)&ob[4]  = o1;
        *(float4*)&ob[8]  = o2;
        *(float4*)&ob[12] = o3;
    }
}

// ---------------------------------------------------------------------------
extern "C" void kernel_launch(void* const* d_in, const int* in_sizes, int n_in,
                              void* d_out, int out_size)
{
    const float* features = (const float*)d_in[0];
    const int*   esrc     = (const int*)d_in[1];
    const int*   edst     = (const int*)d_in[2];
    const float* Ww       = (const float*)d_in[3];
    const float* Wb       = (const float*)d_in[4];
    const float* aw       = (const float*)d_in[5];
    const float* ab       = (const float*)d_in[6];
    float*       out      = (float*)d_out;

    int n = in_sizes[0] / FIN;   // 50000
    int e = in_sizes[1];         // 1600000 (divisible by 4)
    int e4 = e >> 2;

    cudaFuncSetAttribute(gemm_kernel,
                         cudaFuncAttributeMaxDynamicSharedMemorySize,
                         GEMM_SMEM_BYTES);

    // lazy one-time side stream + fork/join events
    static cudaStream_t s2 = nullptr;
    static cudaEvent_t  evFork = nullptr, evJoin = nullptr;
    if (!s2) {
        cudaStreamCreateWithFlags(&s2, cudaStreamNonBlocking);
        cudaEventCreateWithFlags(&evFork, cudaEventDisableTiming);
        cudaEventCreateWithFlags(&evJoin, cudaEventDisableTiming);
    }

    // fork: prep+gemm (tensor/DRAM) on s2, scatter (atomic/L2) on main
    cudaEventRecord(evFork, 0);
    cudaStreamWaitEvent(s2, evFork, 0);
    prep_w_kernel<<<64, 256, 0, s2>>>(Ww);
    gemm_kernel<<<(n + 127) / 128, 256, GEMM_SMEM_BYTES, s2>>>(features, Wb, aw, n);
    cudaEventRecord(evJoin, s2);

    scatter_kernel<<<(e4 + 255) / 256, 256>>>((const int4*)esrc, (const int4*)edst, e4);

    // join: agg needs gemm outputs (keys/scores) and scatter slot lists
    cudaStreamWaitEvent(0, evJoin, 0);
    agg_kernel<<<(n + 31) / 32, 256>>>(ab, out, n);
}